// round 5
// baseline (speedup 1.0000x reference)
#include <cuda_runtime.h>
#include <cuda_fp16.h>
#include <math.h>
#include <cstdint>

#define NROWS 32768
#define DIMS  256
#define CODES 4096
#define BM 64
#define BN 128
#define NCH   (CODES/BN)    // 32
#define NCTAS (NROWS/BM)    // 512
#define GITER (NCH*8)       // 256

// smem byte offsets
#define OFF_AH   0
#define OFF_AL   32768
#define OFF_B    65536
#define B_BUF    10240      // 128 rows * 80B (64B data + 16B pad)
#define OFF_XSQ  106496
#define OFF_RV   106752
#define OFF_RI   107776
#define OFF_LOSS 108800
#define SMEM_SZ  108864

__device__ uint32_t g_xh[NROWS*DIMS/2];
__device__ uint32_t g_xl[NROWS*DIMS/2];
__device__ uint32_t g_eh[CODES*DIMS/2];
__device__ uint32_t g_el[CODES*DIMS/2];
__device__ float  g_xsq[NROWS];
__device__ float  g_esq[CODES];
__device__ int    g_counts[CODES];
__device__ double g_lossPartial[NCTAS];

__device__ __forceinline__ uint32_t smem_u32(const void* p) {
    uint32_t a;
    asm("{ .reg .u64 t; cvta.to.shared.u64 t, %1; cvt.u32.u64 %0, t; }" : "=r"(a) : "l"(p));
    return a;
}
#define CP_ASYNC16(dst, src) \
    asm volatile("cp.async.cg.shared.global [%0], [%1], 16;" :: "r"((uint32_t)(dst)), "l"(src) : "memory")
#define CP_COMMIT() asm volatile("cp.async.commit_group;" ::: "memory")
#define CP_WAIT0()  asm volatile("cp.async.wait_group 0;" ::: "memory")
#define LDM_X4(r, a) \
    asm volatile("ldmatrix.sync.aligned.m8n8.x4.shared.b16 {%0,%1,%2,%3}, [%4];" \
        : "=r"((r)[0]), "=r"((r)[1]), "=r"((r)[2]), "=r"((r)[3]) : "r"(a))
#define MMA16816(c, a, b) \
    asm volatile("mma.sync.aligned.m16n8k16.row.col.f32.f16.f16.f32 " \
        "{%0,%1,%2,%3}, {%4,%5,%6,%7}, {%8,%9}, {%0,%1,%2,%3};" \
        : "+f"((c)[0]), "+f"((c)[1]), "+f"((c)[2]), "+f"((c)[3]) \
        : "r"((a)[0]), "r"((a)[1]), "r"((a)[2]), "r"((a)[3]), "r"((b)[0]), "r"((b)[1]))

__device__ __forceinline__ uint32_t pack_hl(float a, float b, float& ra, float& rb) {
    __half ha = __float2half_rn(a), hb = __float2half_rn(b);
    ra = a - __half2float(ha); rb = b - __half2float(hb);
    return (uint32_t)__half_as_ushort(ha) | ((uint32_t)__half_as_ushort(hb) << 16);
}
__device__ __forceinline__ uint32_t pack_lo(float a, float b) {
    return (uint32_t)__half_as_ushort(__float2half_rn(a)) |
           ((uint32_t)__half_as_ushort(__float2half_rn(b)) << 16);
}

// Fused: one warp per row; computes sq-norm (fp64), writes f16 hi/lo split.
// Codebook rows are pre-scaled by 4096 (exact power-of-2) for the split.
__global__ void k_prep(const float* __restrict__ x, const float* __restrict__ cb) {
    const int wg = (blockIdx.x * blockDim.x + threadIdx.x) >> 5;
    const int lane = threadIdx.x & 31;
    if (wg < NROWS) {
        const int row = wg;
        const float4* p = reinterpret_cast<const float4*>(x) + (size_t)row*64 + lane*2;
        float4 a = p[0], b = p[1];
        double s = (double)a.x*a.x + (double)a.y*a.y + (double)a.z*a.z + (double)a.w*a.w
                 + (double)b.x*b.x + (double)b.y*b.y + (double)b.z*b.z + (double)b.w*b.w;
        #pragma unroll
        for (int o = 16; o > 0; o >>= 1) s += __shfl_down_sync(0xffffffffu, s, o);
        if (lane == 0) g_xsq[row] = (float)s;
        float r0, r1, r2, r3;
        uint32_t h0 = pack_hl(a.x, a.y, r0, r1);
        uint32_t h1 = pack_hl(a.z, a.w, r2, r3);
        uint32_t l0 = pack_lo(r0, r1), l1 = pack_lo(r2, r3);
        uint32_t h2 = pack_hl(b.x, b.y, r0, r1);
        uint32_t h3 = pack_hl(b.z, b.w, r2, r3);
        uint32_t l2 = pack_lo(r0, r1), l3 = pack_lo(r2, r3);
        uint4* dh = (uint4*)(g_xh + (size_t)row*128 + lane*4);
        uint4* dl = (uint4*)(g_xl + (size_t)row*128 + lane*4);
        *dh = make_uint4(h0, h1, h2, h3);
        *dl = make_uint4(l0, l1, l2, l3);
    } else if (wg < NROWS + CODES) {
        const int row = wg - NROWS;
        const float4* p = reinterpret_cast<const float4*>(cb) + (size_t)row*64 + lane*2;
        float4 a = p[0], b = p[1];
        double s = (double)a.x*a.x + (double)a.y*a.y + (double)a.z*a.z + (double)a.w*a.w
                 + (double)b.x*b.x + (double)b.y*b.y + (double)b.z*b.z + (double)b.w*b.w;
        #pragma unroll
        for (int o = 16; o > 0; o >>= 1) s += __shfl_down_sync(0xffffffffu, s, o);
        if (lane == 0) { g_esq[row] = (float)s; g_counts[row] = 0; }
        a.x *= 4096.0f; a.y *= 4096.0f; a.z *= 4096.0f; a.w *= 4096.0f;
        b.x *= 4096.0f; b.y *= 4096.0f; b.z *= 4096.0f; b.w *= 4096.0f;
        float r0, r1, r2, r3;
        uint32_t h0 = pack_hl(a.x, a.y, r0, r1);
        uint32_t h1 = pack_hl(a.z, a.w, r2, r3);
        uint32_t l0 = pack_lo(r0, r1), l1 = pack_lo(r2, r3);
        uint32_t h2 = pack_hl(b.x, b.y, r0, r1);
        uint32_t h3 = pack_hl(b.z, b.w, r2, r3);
        uint32_t l2 = pack_lo(r0, r1), l3 = pack_lo(r2, r3);
        uint4* dh = (uint4*)(g_eh + (size_t)row*128 + lane*4);
        uint4* dl = (uint4*)(g_el + (size_t)row*128 + lane*4);
        *dh = make_uint4(h0, h1, h2, h3);
        *dl = make_uint4(l0, l1, l2, l3);
    }
}

__device__ __forceinline__ void prefetchB(uint32_t smb, int stage, int gc, int t) {
    const int nc = gc >> 3, kch = gc & 7;
    #pragma unroll
    for (int j = 0; j < 4; j++) {
        int i = t + 256*j;
        int arr = i >> 9, rem = i & 511, row = rem >> 2, c = rem & 3;
        uint32_t so = smb + OFF_B + (uint32_t)(stage*2 + arr)*B_BUF + row*80 + c*16;
        const uint8_t* src = (const uint8_t*)(arr ? g_el : g_eh)
                           + (size_t)(nc*BN + row)*512 + (size_t)kch*64 + c*16;
        CP_ASYNC16(so, src);
    }
}

__global__ void __launch_bounds__(256, 2) k_tc(const float* __restrict__ x,
        const float* __restrict__ cb, float* __restrict__ out)
{
    extern __shared__ char sm[];
    const uint32_t smb = smem_u32(sm);
    const int t = threadIdx.x, w = t >> 5, lane = t & 31;
    const int wm = w & 1, wn = w >> 1;          // 2 x 4 warp grid
    const int group = lane >> 2, tid4 = lane & 3;
    const int rowBase = blockIdx.x * BM;

    // A tiles (xh, xl): 64 rows x 256 halves, XOR-swizzled
    #pragma unroll
    for (int j = 0; j < 16; j++) {
        int i = t + 256*j;
        int arr = i >> 11, rem = i & 2047, row = rem >> 5, c = rem & 31;
        uint32_t so = smb + (arr ? OFF_AL : OFF_AH) + row*512 + ((c ^ (row & 7)) * 16);
        const uint8_t* src = (const uint8_t*)(arr ? g_xl : g_xh)
                           + (size_t)(rowBase + row)*512 + c*16;
        CP_ASYNC16(so, src);
    }
    float* sXsq = (float*)(sm + OFF_XSQ);
    for (int i = t; i < BM; i += 256) sXsq[i] = g_xsq[rowBase + i];
    prefetchB(smb, 0, 0, t);
    CP_COMMIT();

    float C[2][4][4];
    float bestV[4];
    int   bestI[4];
    #pragma unroll
    for (int s = 0; s < 4; s++) { bestV[s] = 3.4e38f; bestI[s] = 0; }

    const uint32_t aRow = (uint32_t)(wm*32 + (lane & 15));
    const uint32_t aSwz = (uint32_t)(lane & 7);
    const uint32_t aKhi = (uint32_t)(lane >> 4);

    for (int gi = 0; gi < GITER; ++gi) {
        const int stage = gi & 1;
        CP_WAIT0();
        __syncthreads();
        if (gi + 1 < GITER) { prefetchB(smb, stage ^ 1, gi + 1, t); CP_COMMIT(); }
        if ((gi & 7) == 0) {
            #pragma unroll
            for (int mt = 0; mt < 2; mt++)
                #pragma unroll
                for (int nt = 0; nt < 4; nt++)
                    #pragma unroll
                    for (int q = 0; q < 4; q++) C[mt][nt][q] = 0.0f;
        }
        #pragma unroll
        for (int ks = 0; ks < 2; ++ks) {
            const int kc16 = (gi & 7)*2 + ks;
            uint32_t ah[2][4], al[2][4];
            #pragma unroll
            for (int mt = 0; mt < 2; mt++) {
                uint32_t chunk = ((uint32_t)(kc16*2) + aKhi) ^ aSwz;
                uint32_t ad = smb + OFF_AH + (aRow + mt*16)*512 + chunk*16;
                LDM_X4(ah[mt], ad);
                LDM_X4(al[mt], ad + (OFF_AL - OFF_AH));
            }
            uint32_t bh[4][2], bl[4][2];
            #pragma unroll
            for (int nt = 0; nt < 4; nt++) {
                uint32_t bd = OFF_B + (uint32_t)(stage*2)*B_BUF
                            + (uint32_t)(wn*32 + nt*8 + group)*80 + ks*32 + tid4*4;
                bh[nt][0] = *(const uint32_t*)(sm + bd);
                bh[nt][1] = *(const uint32_t*)(sm + bd + 16);
                bl[nt][0] = *(const uint32_t*)(sm + bd + B_BUF);
                bl[nt][1] = *(const uint32_t*)(sm + bd + B_BUF + 16);
            }
            #pragma unroll
            for (int mt = 0; mt < 2; mt++)
                #pragma unroll
                for (int nt = 0; nt < 4; nt++) {
                    MMA16816(C[mt][nt], ah[mt], bh[nt]);
                    MMA16816(C[mt][nt], al[mt], bh[nt]);
                    MMA16816(C[mt][nt], ah[mt], bl[nt]);
                }
        }
        if ((gi & 7) == 7) {
            const int nc = gi >> 3;
            float e2[4][2];
            #pragma unroll
            for (int nt = 0; nt < 4; nt++)
                #pragma unroll
                for (int q = 0; q < 2; q++)
                    e2[nt][q] = __ldg(g_esq + nc*BN + wn*32 + nt*8 + tid4*2 + q);
            #pragma unroll
            for (int mt = 0; mt < 2; mt++)
                #pragma unroll
                for (int h = 0; h < 2; h++) {
                    const int slot = mt*2 + h;
                    const float xs = sXsq[wm*32 + mt*16 + group + 8*h];
                    #pragma unroll
                    for (int nt = 0; nt < 4; nt++)
                        #pragma unroll
                        for (int q = 0; q < 2; q++) {
                            const int col = nc*BN + wn*32 + nt*8 + tid4*2 + q;
                            const float se = __fadd_rn(xs, e2[nt][q]);
                            const float d = fmaf(-0.00048828125f, C[mt][nt][h*2 + q], se);
                            if (d < bestV[slot]) { bestV[slot] = d; bestI[slot] = col; }
                        }
                }
        }
    }

    // warp-level argmin across tid4 lanes (same row, different cols)
    #pragma unroll
    for (int s = 0; s < 4; s++) {
        #pragma unroll
        for (int o = 1; o <= 2; o <<= 1) {
            float v2 = __shfl_xor_sync(0xffffffffu, bestV[s], o);
            int   i2 = __shfl_xor_sync(0xffffffffu, bestI[s], o);
            if (v2 < bestV[s] || (v2 == bestV[s] && i2 < bestI[s])) {
                bestV[s] = v2; bestI[s] = i2;
            }
        }
    }
    __syncthreads();
    float* sRV = (float*)(sm + OFF_RV);
    int*   sRI = (int*)(sm + OFF_RI);
    if (tid4 == 0) {
        #pragma unroll
        for (int mt = 0; mt < 2; mt++)
            #pragma unroll
            for (int h = 0; h < 2; h++) {
                const int row = wm*32 + mt*16 + group + 8*h;
                sRV[row*4 + wn] = bestV[mt*2 + h];
                sRI[row*4 + wn] = bestI[mt*2 + h];
            }
    }
    __syncthreads();
    if (t < BM) {
        float bv = sRV[t*4];
        int   bi = sRI[t*4];
        #pragma unroll
        for (int j = 1; j < 4; j++) {
            float v = sRV[t*4 + j];
            int   c = sRI[t*4 + j];
            if (v < bv || (v == bv && c < bi)) { bv = v; bi = c; }
        }
        sRI[t*4] = bi;
        atomicAdd(&g_counts[bi], 1);
    }
    __syncthreads();

    // gather + deterministic fp64 loss partial (4 threads per row)
    const int grow = t >> 2, part = t & 3;
    const int best = sRI[grow*4];
    const float4* qs = (const float4*)(cb + (size_t)best*DIMS) + part*16;
    const float4* xs = (const float4*)(x + (size_t)(rowBase + grow)*DIMS) + part*16;
    float4* qd = (float4*)(out + (size_t)(rowBase + grow)*DIMS) + part*16;
    double lsum = 0.0;
    #pragma unroll
    for (int u = 0; u < 16; u++) {
        float4 q = qs[u], xv = xs[u];
        float d0 = q.x - xv.x, d1 = q.y - xv.y, d2 = q.z - xv.z, d3 = q.w - xv.w;
        lsum += (double)d0*d0 + (double)d1*d1 + (double)d2*d2 + (double)d3*d3;
        qd[u] = q;
    }
    #pragma unroll
    for (int o = 16; o > 0; o >>= 1) lsum += __shfl_down_sync(0xffffffffu, lsum, o);
    double* sRed = (double*)(sm + OFF_LOSS);
    if (lane == 0) sRed[w] = lsum;
    __syncthreads();
    if (t == 0) {
        double sa = 0.0;
        #pragma unroll
        for (int k = 0; k < 8; k++) sa += sRed[k];
        g_lossPartial[blockIdx.x] = sa;
    }
}

__global__ void k_final(float* __restrict__ out, int out_size) {
    __shared__ double red[256];
    int t = threadIdx.x;
    double ls = 0.0;
    for (int i = t; i < NCTAS; i += 256) ls += g_lossPartial[i];
    red[t] = ls;
    __syncthreads();
    for (int o = 128; o > 0; o >>= 1) { if (t < o) red[t] += red[t + o]; __syncthreads(); }
    double lossTot = red[0];
    __syncthreads();
    double es = 0.0;
    for (int i = t; i < CODES; i += 256) {
        double p = (double)g_counts[i] * (1.0 / (double)NROWS);
        es += p * log(p + 1e-10);
    }
    red[t] = es;
    __syncthreads();
    for (int o = 128; o > 0; o >>= 1) { if (t < o) red[t] += red[t + o]; __syncthreads(); }
    if (t == 0 && out_size >= NROWS * DIMS + 2) {
        double mse = lossTot / (double)((size_t)NROWS * DIMS);
        out[NROWS * DIMS]     = (float)(mse * 1.25);
        out[NROWS * DIMS + 1] = (float)exp(-red[0]);
    }
}

extern "C" void kernel_launch(void* const* d_in, const int* in_sizes, int n_in,
                              void* d_out, int out_size) {
    const float* x  = (const float*)d_in[0];
    const float* cb = (const float*)d_in[1];
    if (n_in >= 2 && in_sizes[0] == CODES * DIMS && in_sizes[1] == NROWS * DIMS) {
        const float* tmp = x; x = cb; cb = tmp;
    }
    float* out = (float*)d_out;

    cudaFuncSetAttribute(k_tc, cudaFuncAttributeMaxDynamicSharedMemorySize, SMEM_SZ);

    k_prep<<<(NROWS + CODES) / 8, 256>>>(x, cb);
    k_tc<<<NCTAS, 256, SMEM_SZ>>>(x, cb, out);
    k_final<<<1, 256>>>(out, out_size);
}